// round 7
// baseline (speedup 1.0000x reference)
#include <cuda_runtime.h>
#include <math.h>
#include <stdint.h>

#define Bc 4
#define Sc 2048
#define Dc 576
#define Hc 9
#define HDc 64
#define FFc 1536
#define Ec 8
#define Tc (Bc*Sc)          // 8192 tokens
#define NKVc (Hc*2*HDc)     // 1152

// ---------------- scratch (static __device__, no allocation) ----------------
static __device__ __align__(16) float g_xn  [Tc*Dc];
static __device__ __align__(16) float g_q   [Tc*Dc];
static __device__ __align__(16) float g_kv  [Tc*NKVc];
static __device__ __align__(16) float g_ao  [Tc*Dc];
static __device__ __align__(16) float g_x2  [Tc*Dc];
static __device__ __align__(16) float g_xn2 [Tc*Dc];
static __device__ __align__(16) float g_hs  [Tc*FFc];
static __device__ __align__(16) float g_sh  [Tc*Dc];
static __device__ __align__(16) float g_hbuf[2*Tc*FFc];
static __device__ __align__(16) float g_eo  [2*Tc*Dc];
static __device__ int   g_cnt [Ec];
static __device__ int   g_base[Ec];
static __device__ int   g_list[Ec*Tc];
static __device__ int   g_eidx[2*Tc];
static __device__ int   g_epos[2*Tc];
static __device__ float g_wgt [2*Tc];

__device__ __forceinline__ float geluf(float x){
    return 0.5f*x*(1.0f + erff(x*0.70710678118654752f));
}
__device__ __forceinline__ uint32_t f2tf(float x){
    uint32_t r; asm("cvt.rna.tf32.f32 %0, %1;" : "=r"(r) : "f"(x)); return r;
}
__device__ __forceinline__ void mma_tf32(float* c,
    uint32_t a0,uint32_t a1,uint32_t a2,uint32_t a3, uint32_t b0,uint32_t b1){
    asm("mma.sync.aligned.m16n8k8.row.col.f32.tf32.tf32.f32 "
        "{%0,%1,%2,%3},{%4,%5,%6,%7},{%8,%9},{%0,%1,%2,%3};"
        : "+f"(c[0]),"+f"(c[1]),"+f"(c[2]),"+f"(c[3])
        : "r"(a0),"r"(a1),"r"(a2),"r"(a3),"r"(b0),"r"(b1));
}

// ---------------- RMSNorm ----------------
__global__ void rms_kernel(const float* __restrict__ x, float* __restrict__ y){
    int t = blockIdx.x;
    const float* xr = x + (size_t)t*Dc;
    float s = 0.f;
    for (int d = threadIdx.x; d < Dc; d += 256){ float v = xr[d]; s += v*v; }
    #pragma unroll
    for (int o = 16; o; o >>= 1) s += __shfl_xor_sync(0xffffffffu, s, o);
    __shared__ float red[9];
    if ((threadIdx.x & 31) == 0) red[threadIdx.x >> 5] = s;
    __syncthreads();
    if (threadIdx.x == 0){
        float tot = 0.f;
        #pragma unroll
        for (int i = 0; i < 8; i++) tot += red[i];
        red[8] = 1.0f / sqrtf(tot*(1.0f/(float)Dc) + 1e-6f);
    }
    __syncthreads();
    float inv = red[8];
    float* yr = y + (size_t)t*Dc;
    for (int d = threadIdx.x; d < Dc; d += 256) yr[d] = xr[d]*inv;
}

// ---------------- per-token 9x9 head attention (RoPE on q fused) ----------------
__global__ __launch_bounds__(288) void attn_kernel(const float* __restrict__ q,
                                                   const float* __restrict__ kv,
                                                   float* __restrict__ ao)
{
    int t = blockIdx.x;
    int h = threadIdx.x >> 5;
    int lane = threadIdx.x & 31;
    int s = t & (Sc-1);
    int b = t >> 11;

    float theta = exp2f(-0.41524101186092029f*(float)lane); // 10000^(-2*lane/64)
    float fr = (float)s * theta;
    float sn, cs; sincosf(fr, &sn, &cs);

    const float2* qp = (const float2*)(q + (size_t)t*Dc + h*HDc);
    float2 qv = qp[lane];
    float q0 = qv.x*cs - qv.y*sn;
    float q1 = qv.x*sn + qv.y*cs;

    const float* kvb = kv + (size_t)t*NKVc;

    float sc[Hc];
    #pragma unroll
    for (int t9 = 0; t9 < Hc; t9++){
        const float2* kp = (const float2*)(kvb + t9*2*HDc);
        float2 k2 = kp[lane];
        float p = q0*k2.x + q1*k2.y;
        #pragma unroll
        for (int o = 16; o; o >>= 1) p += __shfl_xor_sync(0xffffffffu, p, o);
        sc[t9] = p*0.125f;
    }
    float mx = sc[0];
    #pragma unroll
    for (int t9 = 1; t9 < Hc; t9++) mx = fmaxf(mx, sc[t9]);
    float pr[Hc]; float sum = 0.f;
    #pragma unroll
    for (int t9 = 0; t9 < Hc; t9++){ pr[t9] = expf(sc[t9]-mx); sum += pr[t9]; }
    float inv = 1.0f/sum;

    float o0 = 0.f, o1 = 0.f;
    #pragma unroll
    for (int t9 = 0; t9 < Hc; t9++){
        const float2* vp = (const float2*)(kvb + t9*2*HDc + HDc);
        float2 v2 = vp[lane];
        o0 += pr[t9]*v2.x;
        o1 += pr[t9]*v2.y;
    }
    float2* op = (float2*)(ao + ((((size_t)(b*Hc + h))*Sc + s)*HDc));
    op[lane] = make_float2(o0*inv, o1*inv);
}

// ================= TF32 tensor-core GEMM =================
// 128x64 block tile, 8 warps (4m x 2n), warp tile 32x32, cvt at staging,
// double-buffered smem (one barrier per k-step).

__global__ __launch_bounds__(256) void gemm_tf32(const float* __restrict__ A,
                                                 const float* __restrict__ Bm,
                                                 const float* __restrict__ Res,
                                                 float* __restrict__ C,
                                                 int M, int N, int Kd,
                                                 const int* __restrict__ gather,
                                                 const int* __restrict__ cnts,
                                                 const int* __restrict__ bases,
                                                 long bstride)
{
    __shared__ uint32_t As[2][16][136];
    __shared__ uint32_t Bs[2][16][72];

    int Mloc = M; long base = 0; const int* gl = nullptr;
    if (cnts){
        int e = blockIdx.z;
        Mloc = cnts[e]; base = bases[e];
        Bm += (size_t)e * bstride;
        if (gather) gl = gather + e*Tc;
    }
    int row0 = blockIdx.y*128;
    if (row0 >= Mloc) return;
    int n0 = blockIdx.x*64;

    const int tid  = threadIdx.x;
    const int wid  = tid >> 5;
    const int lane = tid & 31;
    const int wm   = wid & 3;
    const int wn   = wid >> 2;
    const int g    = lane >> 2;
    const int tg   = lane & 3;

    const int lr = tid >> 2, lc = tid & 3;
    int r0l = row0 + lr, r1l = row0 + lr + 64;
    bool v0 = r0l < Mloc, v1 = r1l < Mloc;
    long tok0 = gl ? (v0 ? (long)gl[r0l] : 0) : (base + r0l);
    long tok1 = gl ? (v1 ? (long)gl[r1l] : 0) : (base + r1l);
    const float* Ap0 = A + (size_t)tok0*Kd + lc*4;
    const float* Ap1 = A + (size_t)tok1*Kd + lc*4;
    const int kr = tid >> 4, ncl = tid & 15;
    const float* Bp = Bm + (size_t)kr*N + n0 + ncl*4;

    float acc[2][4][4];
    #pragma unroll
    for (int mt=0; mt<2; mt++)
        #pragma unroll
        for (int nt=0; nt<4; nt++)
            #pragma unroll
            for (int i=0;i<4;i++) acc[mt][nt][i]=0.f;

    const float4 zf = make_float4(0,0,0,0);
    float4 a0p = v0 ? *(const float4*)Ap0 : zf;
    float4 a1p = v1 ? *(const float4*)Ap1 : zf;
    float4 bp  = *(const float4*)Bp;

    // stage k0=0 into buffer 0
    As[0][lc*4+0][lr]    = f2tf(a0p.x); As[0][lc*4+1][lr]    = f2tf(a0p.y);
    As[0][lc*4+2][lr]    = f2tf(a0p.z); As[0][lc*4+3][lr]    = f2tf(a0p.w);
    As[0][lc*4+0][lr+64] = f2tf(a1p.x); As[0][lc*4+1][lr+64] = f2tf(a1p.y);
    As[0][lc*4+2][lr+64] = f2tf(a1p.z); As[0][lc*4+3][lr+64] = f2tf(a1p.w);
    *(uint4*)&Bs[0][kr][ncl*4] =
        make_uint4(f2tf(bp.x),f2tf(bp.y),f2tf(bp.z),f2tf(bp.w));
    __syncthreads();

    int s = 0;
    for (int k0 = 0; k0 < Kd; k0 += 16){
        bool nxt = (k0 + 16) < Kd;
        if (nxt){
            a0p = v0 ? *(const float4*)(Ap0 + k0+16) : zf;
            a1p = v1 ? *(const float4*)(Ap1 + k0+16) : zf;
            bp  = *(const float4*)(Bp + (size_t)(k0+16)*N);
        }
        #pragma unroll
        for (int k8 = 0; k8 < 2; k8++){
            const int kb = k8*8;
            uint32_t af[2][4];
            #pragma unroll
            for (int mt=0; mt<2; mt++){
                int mb = wm*32 + mt*16;
                af[mt][0] = As[s][kb+tg  ][mb+g  ];
                af[mt][1] = As[s][kb+tg  ][mb+g+8];
                af[mt][2] = As[s][kb+tg+4][mb+g  ];
                af[mt][3] = As[s][kb+tg+4][mb+g+8];
            }
            #pragma unroll
            for (int nt=0; nt<4; nt++){
                int nb = wn*32 + nt*8;
                uint32_t b0 = Bs[s][kb+tg  ][nb+g];
                uint32_t b1 = Bs[s][kb+tg+4][nb+g];
                #pragma unroll
                for (int mt=0; mt<2; mt++)
                    mma_tf32(acc[mt][nt], af[mt][0],af[mt][1],af[mt][2],af[mt][3], b0,b1);
            }
        }
        if (nxt){
            int d = s^1;
            As[d][lc*4+0][lr]    = f2tf(a0p.x); As[d][lc*4+1][lr]    = f2tf(a0p.y);
            As[d][lc*4+2][lr]    = f2tf(a0p.z); As[d][lc*4+3][lr]    = f2tf(a0p.w);
            As[d][lc*4+0][lr+64] = f2tf(a1p.x); As[d][lc*4+1][lr+64] = f2tf(a1p.y);
            As[d][lc*4+2][lr+64] = f2tf(a1p.z); As[d][lc*4+3][lr+64] = f2tf(a1p.w);
            *(uint4*)&Bs[d][kr][ncl*4] =
                make_uint4(f2tf(bp.x),f2tf(bp.y),f2tf(bp.z),f2tf(bp.w));
            __syncthreads();
            s = d;
        }
    }

    #pragma unroll
    for (int mt=0; mt<2; mt++){
        #pragma unroll
        for (int nt=0; nt<4; nt++){
            int r = row0 + wm*32 + mt*16 + g;
            int c = n0 + wn*32 + nt*8 + tg*2;
            if (r < Mloc){
                float2 v = make_float2(acc[mt][nt][0], acc[mt][nt][1]);
                if (Res){
                    const float2 rv = *(const float2*)&Res[(size_t)(base+r)*N + c];
                    v.x += rv.x; v.y += rv.y;
                }
                *(float2*)&C[(size_t)(base+r)*N + c] = v;
            }
            if (r + 8 < Mloc){
                float2 v = make_float2(acc[mt][nt][2], acc[mt][nt][3]);
                if (Res){
                    const float2 rv = *(const float2*)&Res[(size_t)(base+r+8)*N + c];
                    v.x += rv.x; v.y += rv.y;
                }
                *(float2*)&C[(size_t)(base+r+8)*N + c] = v;
            }
        }
    }
}

// ----- dual: C = gelu(A@B1)*(A@B3); 128x64 tile, double-buffered -----
__global__ __launch_bounds__(256) void gemm_dual_tf32(const float* __restrict__ A,
                                                      const float* __restrict__ B1,
                                                      const float* __restrict__ B3,
                                                      float* __restrict__ C,
                                                      int M, int N, int Kd,
                                                      const int* __restrict__ gather,
                                                      const int* __restrict__ cnts,
                                                      const int* __restrict__ bases,
                                                      long bstride)
{
    __shared__ uint32_t As [2][16][136];
    __shared__ uint32_t B1s[2][16][72];
    __shared__ uint32_t B3s[2][16][72];

    int Mloc = M; long base = 0; const int* gl = nullptr;
    if (cnts){
        int e = blockIdx.z;
        Mloc = cnts[e]; base = bases[e];
        B1 += (size_t)e * bstride;
        B3 += (size_t)e * bstride;
        if (gather) gl = gather + e*Tc;
    }
    int row0 = blockIdx.y*128;
    if (row0 >= Mloc) return;
    int n0 = blockIdx.x*64;

    const int tid  = threadIdx.x;
    const int wid  = tid >> 5;
    const int lane = tid & 31;
    const int wm   = wid & 3;
    const int wn   = wid >> 2;
    const int g    = lane >> 2;
    const int tg   = lane & 3;

    const int lr = tid >> 2, lc = tid & 3;
    int r0l = row0 + lr, r1l = row0 + lr + 64;
    bool v0 = r0l < Mloc, v1 = r1l < Mloc;
    long tok0 = gl ? (v0 ? (long)gl[r0l] : 0) : (base + r0l);
    long tok1 = gl ? (v1 ? (long)gl[r1l] : 0) : (base + r1l);
    const float* Ap0 = A + (size_t)tok0*Kd + lc*4;
    const float* Ap1 = A + (size_t)tok1*Kd + lc*4;
    const int kr = tid >> 4, ncl = tid & 15;
    const float* B1p = B1 + (size_t)kr*N + n0 + ncl*4;
    const float* B3p = B3 + (size_t)kr*N + n0 + ncl*4;

    float acc1[2][4][4], acc3[2][4][4];
    #pragma unroll
    for (int mt=0; mt<2; mt++)
        #pragma unroll
        for (int nt=0; nt<4; nt++)
            #pragma unroll
            for (int i=0;i<4;i++){ acc1[mt][nt][i]=0.f; acc3[mt][nt][i]=0.f; }

    const float4 zf = make_float4(0,0,0,0);
    float4 a0p = v0 ? *(const float4*)Ap0 : zf;
    float4 a1p = v1 ? *(const float4*)Ap1 : zf;
    float4 b1p = *(const float4*)B1p;
    float4 b3p = *(const float4*)B3p;

    As[0][lc*4+0][lr]    = f2tf(a0p.x); As[0][lc*4+1][lr]    = f2tf(a0p.y);
    As[0][lc*4+2][lr]    = f2tf(a0p.z); As[0][lc*4+3][lr]    = f2tf(a0p.w);
    As[0][lc*4+0][lr+64] = f2tf(a1p.x); As[0][lc*4+1][lr+64] = f2tf(a1p.y);
    As[0][lc*4+2][lr+64] = f2tf(a1p.z); As[0][lc*4+3][lr+64] = f2tf(a1p.w);
    *(uint4*)&B1s[0][kr][ncl*4] =
        make_uint4(f2tf(b1p.x),f2tf(b1p.y),f2tf(b1p.z),f2tf(b1p.w));
    *(uint4*)&B3s[0][kr][ncl*4] =
        make_uint4(f2tf(b3p.x),f2tf(b3p.y),f2tf(b3p.z),f2tf(b3p.w));
    __syncthreads();

    int s = 0;
    for (int k0 = 0; k0 < Kd; k0 += 16){
        bool nxt = (k0 + 16) < Kd;
        if (nxt){
            a0p = v0 ? *(const float4*)(Ap0 + k0+16) : zf;
            a1p = v1 ? *(const float4*)(Ap1 + k0+16) : zf;
            b1p = *(const float4*)(B1p + (size_t)(k0+16)*N);
            b3p = *(const float4*)(B3p + (size_t)(k0+16)*N);
        }
        #pragma unroll
        for (int k8 = 0; k8 < 2; k8++){
            const int kb = k8*8;
            uint32_t af[2][4];
            #pragma unroll
            for (int mt=0; mt<2; mt++){
                int mb = wm*32 + mt*16;
                af[mt][0] = As[s][kb+tg  ][mb+g  ];
                af[mt][1] = As[s][kb+tg  ][mb+g+8];
                af[mt][2] = As[s][kb+tg+4][mb+g  ];
                af[mt][3] = As[s][kb+tg+4][mb+g+8];
            }
            #pragma unroll
            for (int nt=0; nt<4; nt++){
                int nb = wn*32 + nt*8;
                uint32_t b10 = B1s[s][kb+tg  ][nb+g];
                uint32_t b11 = B1s[s][kb+tg+4][nb+g];
                uint32_t b30 = B3s[s][kb+tg  ][nb+g];
                uint32_t b31 = B3s[s][kb+tg+4][nb+g];
                #pragma unroll
                for (int mt=0; mt<2; mt++){
                    mma_tf32(acc1[mt][nt], af[mt][0],af[mt][1],af[mt][2],af[mt][3], b10,b11);
                    mma_tf32(acc3[mt][nt], af[mt][0],af[mt][1],af[mt][2],af[mt][3], b30,b31);
                }
            }
        }
        if (nxt){
            int d = s^1;
            As[d][lc*4+0][lr]    = f2tf(a0p.x); As[d][lc*4+1][lr]    = f2tf(a0p.y);
            As[d][lc*4+2][lr]    = f2tf(a0p.z); As[d][lc*4+3][lr]    = f2tf(a0p.w);
            As[d][lc*4+0][lr+64] = f2tf(a1p.x); As[d][lc*4+1][lr+64] = f2tf(a1p.y);
            As[d][lc*4+2][lr+64] = f2tf(a1p.z); As[d][lc*4+3][lr+64] = f2tf(a1p.w);
            *(uint4*)&B1s[d][kr][ncl*4] =
                make_uint4(f2tf(b1p.x),f2tf(b1p.y),f2tf(b1p.z),f2tf(b1p.w));
            *(uint4*)&B3s[d][kr][ncl*4] =
                make_uint4(f2tf(b3p.x),f2tf(b3p.y),f2tf(b3p.z),f2tf(b3p.w));
            __syncthreads();
            s = d;
        }
    }

    #pragma unroll
    for (int mt=0; mt<2; mt++){
        #pragma unroll
        for (int nt=0; nt<4; nt++){
            int r = row0 + wm*32 + mt*16 + g;
            int c = n0 + wn*32 + nt*8 + tg*2;
            if (r < Mloc){
                float2 v;
                v.x = geluf(acc1[mt][nt][0])*acc3[mt][nt][0];
                v.y = geluf(acc1[mt][nt][1])*acc3[mt][nt][1];
                *(float2*)&C[(size_t)(base+r)*N + c] = v;
            }
            if (r + 8 < Mloc){
                float2 v;
                v.x = geluf(acc1[mt][nt][2])*acc3[mt][nt][2];
                v.y = geluf(acc1[mt][nt][3])*acc3[mt][nt][3];
                *(float2*)&C[(size_t)(base+r+8)*N + c] = v;
            }
        }
    }
}

// ---------------- gate + top-2 + token gather lists ----------------
__global__ void zero_cnt_kernel(int* cnt){ if (threadIdx.x < Ec) cnt[threadIdx.x] = 0; }

__global__ void gate_kernel(const float* __restrict__ xn2,
                            const float* __restrict__ gw,
                            int* __restrict__ cnt,
                            int* __restrict__ list,
                            int* __restrict__ eidx,
                            int* __restrict__ epos,
                            float* __restrict__ wgt)
{
    int warp = threadIdx.x >> 5;
    int lane = threadIdx.x & 31;
    int t = blockIdx.x*4 + warp;
    float acc[Ec];
    #pragma unroll
    for (int e = 0; e < Ec; e++) acc[e] = 0.f;
    const float* xr = xn2 + (size_t)t*Dc;
    for (int k = lane; k < Dc; k += 32){
        float xv = xr[k];
        #pragma unroll
        for (int e = 0; e < Ec; e++) acc[e] += xv * gw[k*Ec + e];
    }
    #pragma unroll
    for (int e = 0; e < Ec; e++){
        #pragma unroll
        for (int o = 16; o; o >>= 1) acc[e] += __shfl_xor_sync(0xffffffffu, acc[e], o);
    }
    if (lane == 0){
        float mx = acc[0];
        #pragma unroll
        for (int e = 1; e < Ec; e++) mx = fmaxf(mx, acc[e]);
        float p[Ec];
        #pragma unroll
        for (int e = 0; e < Ec; e++) p[e] = expf(acc[e] - mx);
        int i0 = 0;
        #pragma unroll
        for (int e = 1; e < Ec; e++) if (p[e] > p[i0]) i0 = e;
        int i1 = (i0 == 0) ? 1 : 0;
        #pragma unroll
        for (int e = 0; e < Ec; e++) if (e != i0 && p[e] > p[i1]) i1 = e;
        float tot = p[i0] + p[i1];
        float w0 = p[i0]/tot, w1 = p[i1]/tot;
        int pos0 = atomicAdd(&cnt[i0], 1);
        int pos1 = atomicAdd(&cnt[i1], 1);
        list[i0*Tc + pos0] = t;
        list[i1*Tc + pos1] = t;
        eidx[2*t]   = i0; epos[2*t]   = pos0; wgt[2*t]   = w0;
        eidx[2*t+1] = i1; epos[2*t+1] = pos1; wgt[2*t+1] = w1;
    }
}

__global__ void prefix_kernel(const int* __restrict__ cnt, int* __restrict__ base){
    if (threadIdx.x == 0){
        int a = 0;
        #pragma unroll
        for (int e = 0; e < Ec; e++){ base[e] = a; a += cnt[e]; }
    }
}

// ---------------- final combine ----------------
__global__ void combine_kernel(const float* __restrict__ x2,
                               const float* __restrict__ sh,
                               const float* __restrict__ eo,
                               const int* __restrict__ eidx,
                               const int* __restrict__ epos,
                               const int* __restrict__ bases,
                               const float* __restrict__ wgt,
                               float* __restrict__ out)
{
    int t = blockIdx.x;
    int g0 = bases[eidx[2*t]]   + epos[2*t];
    int g1 = bases[eidx[2*t+1]] + epos[2*t+1];
    float w0 = wgt[2*t], w1 = wgt[2*t+1];
    int d = threadIdx.x*4;
    size_t o = (size_t)t*Dc + d;
    float4 a  = *(const float4*)&x2[o];
    float4 b  = *(const float4*)&sh[o];
    float4 c0 = *(const float4*)&eo[(size_t)g0*Dc + d];
    float4 c1 = *(const float4*)&eo[(size_t)g1*Dc + d];
    float4 r;
    r.x = a.x + b.x + w0*c0.x + w1*c1.x;
    r.y = a.y + b.y + w0*c0.y + w1*c1.y;
    r.z = a.z + b.z + w0*c0.z + w1*c1.z;
    r.w = a.w + b.w + w0*c0.w + w1*c1.w;
    *(float4*)&out[o] = r;
}

// ---------------- launch ----------------
extern "C" void kernel_launch(void* const* d_in, const int* in_sizes, int n_in,
                              void* d_out, int out_size)
{
    const float* x   = (const float*)d_in[0];
    const float* qw  = (const float*)d_in[1];
    const float* kvw = (const float*)d_in[2];
    const float* ow  = (const float*)d_in[3];
    const float* gw  = (const float*)d_in[4];
    const float* w1  = (const float*)d_in[5];
    const float* w2  = (const float*)d_in[6];
    const float* w3  = (const float*)d_in[7];
    const float* sw1 = (const float*)d_in[8];
    const float* sw2 = (const float*)d_in[9];
    const float* sw3 = (const float*)d_in[10];
    float* out = (float*)d_out;

    float *xn,*qb,*kvb,*ao,*x2,*xn2,*hs,*sh,*hbuf,*eo,*wgt;
    int *cnt,*base,*list,*eidx,*epos;
    cudaGetSymbolAddress((void**)&xn,   g_xn);
    cudaGetSymbolAddress((void**)&qb,   g_q);
    cudaGetSymbolAddress((void**)&kvb,  g_kv);
    cudaGetSymbolAddress((void**)&ao,   g_ao);
    cudaGetSymbolAddress((void**)&x2,   g_x2);
    cudaGetSymbolAddress((void**)&xn2,  g_xn2);
    cudaGetSymbolAddress((void**)&hs,   g_hs);
    cudaGetSymbolAddress((void**)&sh,   g_sh);
    cudaGetSymbolAddress((void**)&hbuf, g_hbuf);
    cudaGetSymbolAddress((void**)&eo,   g_eo);
    cudaGetSymbolAddress((void**)&wgt,  g_wgt);
    cudaGetSymbolAddress((void**)&cnt,  g_cnt);
    cudaGetSymbolAddress((void**)&base, g_base);
    cudaGetSymbolAddress((void**)&list, g_list);
    cudaGetSymbolAddress((void**)&eidx, g_eidx);
    cudaGetSymbolAddress((void**)&epos, g_epos);

    // 1. rms1
    rms_kernel<<<Tc, 256>>>(x, xn);
    // 2. q / kv projections (tf32)
    gemm_tf32<<<dim3(Dc/64,   Tc/128, 1), 256>>>(xn, qw,  nullptr, qb,  Tc, Dc,   Dc,
                                                 nullptr, nullptr, nullptr, 0);
    gemm_tf32<<<dim3(NKVc/64, Tc/128, 1), 256>>>(xn, kvw, nullptr, kvb, Tc, NKVc, Dc,
                                                 nullptr, nullptr, nullptr, 0);
    // 3. per-token 9x9 head attention (rope fused)
    attn_kernel<<<Tc, 288>>>(qb, kvb, ao);
    // 4. O-proj + residual
    gemm_tf32<<<dim3(Dc/64, Tc/128, 1), 256>>>(ao, ow, x, x2, Tc, Dc, Dc,
                                               nullptr, nullptr, nullptr, 0);
    // 5. rms2
    rms_kernel<<<Tc, 256>>>(x2, xn2);
    // 6. gate + top2 + gather lists
    zero_cnt_kernel<<<1, 32>>>(cnt);
    gate_kernel<<<Tc/4, 128>>>(xn2, gw, cnt, list, eidx, epos, wgt);
    prefix_kernel<<<1, 32>>>(cnt, base);
    // 7. shared expert
    gemm_dual_tf32<<<dim3(FFc/64, Tc/128, 1), 256>>>(xn2, sw1, sw3, hs, Tc, FFc, Dc,
                                                     nullptr, nullptr, nullptr, 0);
    gemm_tf32<<<dim3(Dc/64, Tc/128, 1), 256>>>(hs, sw2, nullptr, sh, Tc, Dc, FFc,
                                               nullptr, nullptr, nullptr, 0);
    // 8. MoE experts (sparse, gathered)
    gemm_dual_tf32<<<dim3(FFc/64, Tc/128, Ec), 256>>>(xn2, w1, w3, hbuf, Tc, FFc, Dc,
                                                      list, cnt, base, (long)Dc*FFc);
    gemm_tf32<<<dim3(Dc/64, Tc/128, Ec), 256>>>(hbuf, w2, nullptr, eo, Tc, Dc, FFc,
                                                nullptr, cnt, base, (long)FFc*Dc);
    // 9. out = x2 + shared + w0*eo0 + w1*eo1
    combine_kernel<<<Tc, 144>>>(x2, sh, eo, eidx, epos, base, wgt, out);
}

// round 9
// speedup vs baseline: 1.3661x; 1.3661x over previous
#include <cuda_runtime.h>
#include <cuda_fp16.h>
#include <math.h>
#include <stdint.h>

#define Bc 4
#define Sc 2048
#define Dc 576
#define Hc 9
#define HDc 64
#define FFc 1536
#define Ec 8
#define Tc (Bc*Sc)
#define NKVc (Hc*2*HDc)

// ---------------- scratch ----------------
static __device__ __align__(16) float g_xn  [Tc*Dc];
static __device__ __align__(16) float g_q   [Tc*Dc];
static __device__ __align__(16) float g_kv  [Tc*NKVc];
static __device__ __align__(16) float g_ao  [Tc*Dc];
static __device__ __align__(16) float g_x2  [Tc*Dc];
static __device__ __align__(16) float g_xn2 [Tc*Dc];
static __device__ __align__(16) float g_hs  [Tc*FFc];
static __device__ __align__(16) float g_sh  [Tc*Dc];
static __device__ __align__(16) float g_hbuf[2*Tc*FFc];
static __device__ __align__(16) float g_eo  [2*Tc*Dc];
// fp16 transposed weights [N][K]
static __device__ __align__(16) __half g_qwT [Dc*Dc];
static __device__ __align__(16) __half g_kvwT[NKVc*Dc];
static __device__ __align__(16) __half g_owT [Dc*Dc];
static __device__ __align__(16) __half g_sw1T[FFc*Dc];
static __device__ __align__(16) __half g_sw3T[FFc*Dc];
static __device__ __align__(16) __half g_sw2T[Dc*FFc];
static __device__ __align__(16) __half g_w1T [Ec*FFc*Dc];
static __device__ __align__(16) __half g_w3T [Ec*FFc*Dc];
static __device__ __align__(16) __half g_w2T [Ec*Dc*FFc];
static __device__ int   g_cnt [Ec];
static __device__ int   g_base[Ec];
static __device__ int   g_list[Ec*Tc];
static __device__ int   g_eidx[2*Tc];
static __device__ int   g_epos[2*Tc];
static __device__ float g_wgt [2*Tc];

__device__ __forceinline__ float geluf(float x){
    return 0.5f*x*(1.0f + erff(x*0.70710678118654752f));
}
// pack two floats to f16x2: lo = first arg
__device__ __forceinline__ uint32_t pack2(float lo, float hi){
    uint32_t r; asm("cvt.rn.f16x2.f32 %0, %1, %2;" : "=r"(r) : "f"(hi), "f"(lo)); return r;
}
__device__ __forceinline__ uint2 pack4(float4 v){
    return make_uint2(pack2(v.x, v.y), pack2(v.z, v.w));
}
__device__ __forceinline__ void mma_f16(float* c,
    uint32_t a0,uint32_t a1,uint32_t a2,uint32_t a3, uint32_t b0,uint32_t b1){
    asm("mma.sync.aligned.m16n8k16.row.col.f32.f16.f16.f32 "
        "{%0,%1,%2,%3},{%4,%5,%6,%7},{%8,%9},{%0,%1,%2,%3};"
        : "+f"(c[0]),"+f"(c[1]),"+f"(c[2]),"+f"(c[3])
        : "r"(a0),"r"(a1),"r"(a2),"r"(a3),"r"(b0),"r"(b1));
}

// ---------------- weight transpose fp32[K][N] -> fp16[N][K] ----------------
__global__ void transp_kernel(const float* __restrict__ src, __half* __restrict__ dst,
                              int K, int N){
    __shared__ float tile[32][33];
    src += (size_t)blockIdx.z*K*N; dst += (size_t)blockIdx.z*(size_t)K*N;
    int k0 = blockIdx.y*32, n0 = blockIdx.x*32;
    for (int i = threadIdx.y; i < 32; i += 8)
        tile[i][threadIdx.x] = src[(size_t)(k0+i)*N + n0 + threadIdx.x];
    __syncthreads();
    for (int i = threadIdx.y; i < 32; i += 8)
        dst[(size_t)(n0+i)*K + k0 + threadIdx.x] = __float2half(tile[threadIdx.x][i]);
}

// ---------------- RMSNorm ----------------
__global__ void rms_kernel(const float* __restrict__ x, float* __restrict__ y){
    int t = blockIdx.x;
    const float* xr = x + (size_t)t*Dc;
    float s = 0.f;
    for (int d = threadIdx.x; d < Dc; d += 256){ float v = xr[d]; s += v*v; }
    #pragma unroll
    for (int o = 16; o; o >>= 1) s += __shfl_xor_sync(0xffffffffu, s, o);
    __shared__ float red[9];
    if ((threadIdx.x & 31) == 0) red[threadIdx.x >> 5] = s;
    __syncthreads();
    if (threadIdx.x == 0){
        float tot = 0.f;
        #pragma unroll
        for (int i = 0; i < 8; i++) tot += red[i];
        red[8] = 1.0f / sqrtf(tot*(1.0f/(float)Dc) + 1e-6f);
    }
    __syncthreads();
    float inv = red[8];
    float* yr = y + (size_t)t*Dc;
    for (int d = threadIdx.x; d < Dc; d += 256) yr[d] = xr[d]*inv;
}

// ---------------- per-token 9x9 head attention (RoPE fused) ----------------
__global__ __launch_bounds__(288) void attn_kernel(const float* __restrict__ q,
                                                   const float* __restrict__ kv,
                                                   float* __restrict__ ao)
{
    int t = blockIdx.x;
    int h = threadIdx.x >> 5;
    int lane = threadIdx.x & 31;
    int s = t & (Sc-1);
    int b = t >> 11;
    float theta = exp2f(-0.41524101186092029f*(float)lane);
    float fr = (float)s * theta;
    float sn, cs; sincosf(fr, &sn, &cs);
    const float2* qp = (const float2*)(q + (size_t)t*Dc + h*HDc);
    float2 qv = qp[lane];
    float q0 = qv.x*cs - qv.y*sn;
    float q1 = qv.x*sn + qv.y*cs;
    const float* kvb = kv + (size_t)t*NKVc;
    float sc[Hc];
    #pragma unroll
    for (int t9 = 0; t9 < Hc; t9++){
        const float2* kp = (const float2*)(kvb + t9*2*HDc);
        float2 k2 = kp[lane];
        float p = q0*k2.x + q1*k2.y;
        #pragma unroll
        for (int o = 16; o; o >>= 1) p += __shfl_xor_sync(0xffffffffu, p, o);
        sc[t9] = p*0.125f;
    }
    float mx = sc[0];
    #pragma unroll
    for (int t9 = 1; t9 < Hc; t9++) mx = fmaxf(mx, sc[t9]);
    float pr[Hc]; float sum = 0.f;
    #pragma unroll
    for (int t9 = 0; t9 < Hc; t9++){ pr[t9] = expf(sc[t9]-mx); sum += pr[t9]; }
    float inv = 1.0f/sum;
    float o0 = 0.f, o1 = 0.f;
    #pragma unroll
    for (int t9 = 0; t9 < Hc; t9++){
        const float2* vp = (const float2*)(kvb + t9*2*HDc + HDc);
        float2 v2 = vp[lane];
        o0 += pr[t9]*v2.x;
        o1 += pr[t9]*v2.y;
    }
    float2* op = (float2*)(ao + ((((size_t)(b*Hc + h))*Sc + s)*HDc));
    op[lane] = make_float2(o0*inv, o1*inv);
}

// ================= fp16 mma GEMM: 128x64 tile, k-step 32, double-buffered =================
// As[buf][k8half 0..3][row 0..127][word 0..3]  (word = half2, 16B rows -> conflict-free)
// Bs[buf][k8half][n 0..63][word]
__global__ __launch_bounds__(256,2) void gemm_f16(const float* __restrict__ A,
                                                  const __half* __restrict__ BT,
                                                  const float* __restrict__ Res,
                                                  float* __restrict__ C,
                                                  int N, int Kd,
                                                  const int* __restrict__ gather,
                                                  const int* __restrict__ cnts,
                                                  const int* __restrict__ bases,
                                                  long bstride)
{
    __shared__ uint32_t As[2][4][128][4];
    __shared__ uint32_t Bs[2][4][64][4];

    int Mloc = Tc; long base = 0; const int* gl = nullptr;
    if (cnts){
        int e = blockIdx.z;
        Mloc = cnts[e]; base = bases[e];
        BT += (size_t)e*bstride;
        if (gather) gl = gather + e*Tc;
    }
    int row0 = blockIdx.y*128;
    if (row0 >= Mloc) return;
    int n0 = blockIdx.x*64;

    const int tid = threadIdx.x, wid = tid>>5, lane = tid&31;
    const int wm = wid & 3, wn = wid >> 2;
    const int g = lane >> 2, tg = lane & 3;

    // A loader: rows lr, lr+64; float4 pairs at k = lc*4 and lc*4+16
    const int lr = tid >> 2, lc = tid & 3;
    int r0l = row0 + lr, r1l = row0 + lr + 64;
    bool v0 = r0l < Mloc, v1 = r1l < Mloc;
    long tok0 = gl ? (v0 ? (long)gl[r0l] : 0) : (base + r0l);
    long tok1 = gl ? (v1 ? (long)gl[r1l] : 0) : (base + r1l);
    const float* Ap0 = A + (size_t)tok0*Kd + lc*4;
    const float* Ap1 = A + (size_t)tok1*Kd + lc*4;
    const int kh0 = lc >> 1, wp = (lc & 1)*2;
    // B loader: n = tid>>2, k8half = tid&3 (16B per thread per chunk)
    const __half* Bp = BT + (size_t)(n0 + (tid>>2))*Kd + (tid&3)*8;

    float acc[2][4][4];
    #pragma unroll
    for (int mt=0; mt<2; mt++)
        #pragma unroll
        for (int nt=0; nt<4; nt++)
            #pragma unroll
            for (int i=0;i<4;i++) acc[mt][nt][i]=0.f;

    const float4 zf = make_float4(0,0,0,0);
    float4 a00 = v0 ? *(const float4*)Ap0        : zf;
    float4 a01 = v0 ? *(const float4*)(Ap0 + 16) : zf;
    float4 a10 = v1 ? *(const float4*)Ap1        : zf;
    float4 a11 = v1 ? *(const float4*)(Ap1 + 16) : zf;
    uint4  bp  = *(const uint4*)Bp;

    // stage chunk 0 into buffer 0
    *(uint2*)&As[0][kh0  ][lr   ][wp] = pack4(a00);
    *(uint2*)&As[0][kh0+2][lr   ][wp] = pack4(a01);
    *(uint2*)&As[0][kh0  ][lr+64][wp] = pack4(a10);
    *(uint2*)&As[0][kh0+2][lr+64][wp] = pack4(a11);
    *(uint4*)&Bs[0][tid&3][tid>>2][0] = bp;
    __syncthreads();

    int nc = Kd >> 5;
    int s = 0;
    for (int c = 0; c < nc; c++){
        bool nxt = (c + 1) < nc;
        if (nxt){
            int k0 = (c+1) << 5;
            a00 = v0 ? *(const float4*)(Ap0 + k0)      : zf;
            a01 = v0 ? *(const float4*)(Ap0 + k0 + 16) : zf;
            a10 = v1 ? *(const float4*)(Ap1 + k0)      : zf;
            a11 = v1 ? *(const float4*)(Ap1 + k0 + 16) : zf;
            bp  = *(const uint4*)(Bp + k0);
        }
        #pragma unroll
        for (int h = 0; h < 2; h++){
            const int kb = h*2;
            uint32_t af[2][4];
            #pragma unroll
            for (int mt=0; mt<2; mt++){
                int mb = wm*32 + mt*16;
                af[mt][0] = As[s][kb  ][mb+g  ][tg];
                af[mt][1] = As[s][kb  ][mb+g+8][tg];
                af[mt][2] = As[s][kb+1][mb+g  ][tg];
                af[mt][3] = As[s][kb+1][mb+g+8][tg];
            }
            #pragma unroll
            for (int nt=0; nt<4; nt++){
                int nb = wn*32 + nt*8;
                uint32_t b0 = Bs[s][kb  ][nb+g][tg];
                uint32_t b1 = Bs[s][kb+1][nb+g][tg];
                #pragma unroll
                for (int mt=0; mt<2; mt++)
                    mma_f16(acc[mt][nt], af[mt][0],af[mt][1],af[mt][2],af[mt][3], b0,b1);
            }
        }
        if (nxt){
            int d = s^1;
            *(uint2*)&As[d][kh0  ][lr   ][wp] = pack4(a00);
            *(uint2*)&As[d][kh0+2][lr   ][wp] = pack4(a01);
            *(uint2*)&As[d][kh0  ][lr+64][wp] = pack4(a10);
            *(uint2*)&As[d][kh0+2][lr+64][wp] = pack4(a11);
            *(uint4*)&Bs[d][tid&3][tid>>2][0] = bp;
            __syncthreads();
            s = d;
        }
    }

    #pragma unroll
    for (int mt=0; mt<2; mt++){
        #pragma unroll
        for (int nt=0; nt<4; nt++){
            int r = row0 + wm*32 + mt*16 + g;
            int c = n0 + wn*32 + nt*8 + tg*2;
            if (r < Mloc){
                float2 v = make_float2(acc[mt][nt][0], acc[mt][nt][1]);
                if (Res){
                    const float2 rv = *(const float2*)&Res[(size_t)(base+r)*N + c];
                    v.x += rv.x; v.y += rv.y;
                }
                *(float2*)&C[(size_t)(base+r)*N + c] = v;
            }
            if (r + 8 < Mloc){
                float2 v = make_float2(acc[mt][nt][2], acc[mt][nt][3]);
                if (Res){
                    const float2 rv = *(const float2*)&Res[(size_t)(base+r+8)*N + c];
                    v.x += rv.x; v.y += rv.y;
                }
                *(float2*)&C[(size_t)(base+r+8)*N + c] = v;
            }
        }
    }
}

// ----- dual: C = gelu(A@B1T^T)*(A@B3T^T) -----
__global__ __launch_bounds__(256,2) void gemm_dual_f16(const float* __restrict__ A,
                                                       const __half* __restrict__ B1T,
                                                       const __half* __restrict__ B3T,
                                                       float* __restrict__ C,
                                                       int N, int Kd,
                                                       const int* __restrict__ gather,
                                                       const int* __restrict__ cnts,
                                                       const int* __restrict__ bases,
                                                       long bstride)
{
    __shared__ uint32_t As [2][4][128][4];
    __shared__ uint32_t B1s[2][4][64][4];
    __shared__ uint32_t B3s[2][4][64][4];

    int Mloc = Tc; long base = 0; const int* gl = nullptr;
    if (cnts){
        int e = blockIdx.z;
        Mloc = cnts[e]; base = bases[e];
        B1T += (size_t)e*bstride;
        B3T += (size_t)e*bstride;
        if (gather) gl = gather + e*Tc;
    }
    int row0 = blockIdx.y*128;
    if (row0 >= Mloc) return;
    int n0 = blockIdx.x*64;

    const int tid = threadIdx.x, wid = tid>>5, lane = tid&31;
    const int wm = wid & 3, wn = wid >> 2;
    const int g = lane >> 2, tg = lane & 3;

    const int lr = tid >> 2, lc = tid & 3;
    int r0l = row0 + lr, r1l = row0 + lr + 64;
    bool v0 = r0l < Mloc, v1 = r1l < Mloc;
    long tok0 = gl ? (v0 ? (long)gl[r0l] : 0) : (base + r0l);
    long tok1 = gl ? (v1 ? (long)gl[r1l] : 0) : (base + r1l);
    const float* Ap0 = A + (size_t)tok0*Kd + lc*4;
    const float* Ap1 = A + (size_t)tok1*Kd + lc*4;
    const int kh0 = lc >> 1, wp = (lc & 1)*2;
    const __half* B1p = B1T + (size_t)(n0 + (tid>>2))*Kd + (tid&3)*8;
    const __half* B3p = B3T + (size_t)(n0 + (tid>>2))*Kd + (tid&3)*8;

    float acc1[2][4][4], acc3[2][4][4];
    #pragma unroll
    for (int mt=0; mt<2; mt++)
        #pragma unroll
        for (int nt=0; nt<4; nt++)
            #pragma unroll
            for (int i=0;i<4;i++){ acc1[mt][nt][i]=0.f; acc3[mt][nt][i]=0.f; }

    const float4 zf = make_float4(0,0,0,0);
    float4 a00 = v0 ? *(const float4*)Ap0        : zf;
    float4 a01 = v0 ? *(const float4*)(Ap0 + 16) : zf;
    float4 a10 = v1 ? *(const float4*)Ap1        : zf;
    float4 a11 = v1 ? *(const float4*)(Ap1 + 16) : zf;
    uint4  b1p = *(const uint4*)B1p;
    uint4  b3p = *(const uint4*)B3p;

    *(uint2*)&As[0][kh0  ][lr   ][wp] = pack4(a00);
    *(uint2*)&As[0][kh0+2][lr   ][wp] = pack4(a01);
    *(uint2*)&As[0][kh0  ][lr+64][wp] = pack4(a10);
    *(uint2*)&As[0][kh0+2][lr+64][wp] = pack4(a11);
    *(uint4*)&B1s[0][tid&3][tid>>2][0] = b1p;
    *(uint4*)&B3s[0][tid&3][tid>>2][0] = b3p;
    __syncthreads();

    int nc = Kd >> 5;
    int s = 0;
    for (int c = 0; c < nc; c++){
        bool nxt = (c + 1) < nc;
        if (nxt){
            int k0 = (c+1) << 5;
            a00 = v0 ? *(const float4*)(Ap0 + k0)      : zf;
            a01 = v0 ? *(const float4*)(Ap0 + k0 + 16) : zf;
            a10 = v1 ? *(const float4*)(Ap1 + k0)      : zf;
            a11 = v1 ? *(const float4*)(Ap1 + k0 + 16) : zf;
            b1p = *(const uint4*)(B1p + k0);
            b3p = *(const uint4*)(B3p + k0);
        }
        #pragma unroll
        for (int h = 0; h < 2; h++){
            const int kb = h*2;
            uint32_t af[2][4];
            #pragma unroll
            for (int mt=0; mt<2; mt++){
                int mb = wm*32 + mt*16;
                af[mt][0] = As[s][kb  ][mb+g  ][tg];
                af[mt][1] = As[s][kb  ][mb+g+8][tg];
                af[mt][2] = As[s][kb+1][mb+g  ][tg];
                af[mt][3] = As[s][kb+1][mb+g+8][tg];
            }
            #pragma unroll
            for (int nt=0; nt<4; nt++){
                int nb = wn*32 + nt*8;
                uint32_t b10 = B1s[s][kb  ][nb+g][tg];
                uint32_t b11 = B1s[s][kb+1][nb+g][tg];
                uint32_t b30 = B3s[s][kb  ][nb+g][tg];
                uint32_t b31 = B3s[s][kb+1][nb+g][tg];
                #pragma unroll
                for (int mt=0; mt<2; mt++){
                    mma_f16(acc1[mt][nt], af[mt][0],af[mt][1],af[mt][2],af[mt][3], b10,b11);
                    mma_f16(acc3[mt][nt], af[mt][0],af[mt][1],af[mt][2],af[mt][3], b30,b31);
                }
            }
        }
        if (nxt){
            int d = s^1;
            *(uint2*)&As[d][kh0  ][lr   ][wp] = pack4(a00);
            *(uint2*)&As[d][kh0+2][lr   ][wp] = pack4(a01);
            *(uint2*)&As[d][kh0  ][lr+64][wp] = pack4(a10);
            *(uint2*)&As[d][kh0+2][lr+64][wp] = pack4(a11);
            *(uint4*)&B1s[d][tid&3][tid>>2][0] = b1p;
            *(uint4*)&B3s[d][tid&3][tid>>2][0] = b3p;
            __syncthreads();
            s = d;
        }
    }

    #pragma unroll
    for (int mt=0; mt<2; mt++){
        #pragma unroll
        for (int nt=0; nt<4; nt++){
            int r = row0 + wm*32 + mt*16 + g;
            int c = n0 + wn*32 + nt*8 + tg*2;
            if (r < Mloc){
                float2 v;
                v.x = geluf(acc1[mt][nt][0])*acc3[mt][nt][0];
                v.y = geluf(acc1[mt][nt][1])*acc3[mt][nt][1];
                *(float2*)&C[(size_t)(base+r)*N + c] = v;
            }
            if (r + 8 < Mloc){
                float2 v;
                v.x = geluf(acc1[mt][nt][2])*acc3[mt][nt][2];
                v.y = geluf(acc1[mt][nt][3])*acc3[mt][nt][3];
                *(float2*)&C[(size_t)(base+r+8)*N + c] = v;
            }
        }
    }
}

// ---------------- gate + top-2 ----------------
__global__ void zero_cnt_kernel(int* cnt){ if (threadIdx.x < Ec) cnt[threadIdx.x] = 0; }

__global__ void gate_kernel(const float* __restrict__ xn2,
                            const float* __restrict__ gw,
                            int* __restrict__ cnt, int* __restrict__ list,
                            int* __restrict__ eidx, int* __restrict__ epos,
                            float* __restrict__ wgt)
{
    int warp = threadIdx.x >> 5;
    int lane = threadIdx.x & 31;
    int t = blockIdx.x*4 + warp;
    float acc[Ec];
    #pragma unroll
    for (int e = 0; e < Ec; e++) acc[e] = 0.f;
    const float* xr = xn2 + (size_t)t*Dc;
    for (int k = lane; k < Dc; k += 32){
        float xv = xr[k];
        #pragma unroll
        for (int e = 0; e < Ec; e++) acc[e] += xv * gw[k*Ec + e];
    }
    #pragma unroll
    for (int e = 0; e < Ec; e++){
        #pragma unroll
        for (int o = 16; o; o >>= 1) acc[e] += __shfl_xor_sync(0xffffffffu, acc[e], o);
    }
    if (lane == 0){
        float mx = acc[0];
        #pragma unroll
        for (int e = 1; e < Ec; e++) mx = fmaxf(mx, acc[e]);
        float p[Ec];
        #pragma unroll
        for (int e = 0; e < Ec; e++) p[e] = expf(acc[e] - mx);
        int i0 = 0;
        #pragma unroll
        for (int e = 1; e < Ec; e++) if (p[e] > p[i0]) i0 = e;
        int i1 = (i0 == 0) ? 1 : 0;
        #pragma unroll
        for (int e = 0; e < Ec; e++) if (e != i0 && p[e] > p[i1]) i1 = e;
        float tot = p[i0] + p[i1];
        float w0 = p[i0]/tot, w1 = p[i1]/tot;
        int pos0 = atomicAdd(&cnt[i0], 1);
        int pos1 = atomicAdd(&cnt[i1], 1);
        list[i0*Tc + pos0] = t;
        list[i1*Tc + pos1] = t;
        eidx[2*t]   = i0; epos[2*t]   = pos0; wgt[2*t]   = w0;
        eidx[2*t+1] = i1; epos[2*t+1] = pos1; wgt[2*t+1] = w1;
    }
}

__global__ void prefix_kernel(const int* __restrict__ cnt, int* __restrict__ base){
    if (threadIdx.x == 0){
        int a = 0;
        #pragma unroll
        for (int e = 0; e < Ec; e++){ base[e] = a; a += cnt[e]; }
    }
}

// ---------------- final combine ----------------
__global__ void combine_kernel(const float* __restrict__ x2, const float* __restrict__ sh,
                               const float* __restrict__ eo, const int* __restrict__ eidx,
                               const int* __restrict__ epos, const int* __restrict__ bases,
                               const float* __restrict__ wgt, float* __restrict__ out)
{
    int t = blockIdx.x;
    int g0 = bases[eidx[2*t]]   + epos[2*t];
    int g1 = bases[eidx[2*t+1]] + epos[2*t+1];
    float w0 = wgt[2*t], w1 = wgt[2*t+1];
    int d = threadIdx.x*4;
    size_t o = (size_t)t*Dc + d;
    float4 a  = *(const float4*)&x2[o];
    float4 b  = *(const float4*)&sh[o];
    float4 c0 = *(const float4*)&eo[(size_t)g0*Dc + d];
    float4 c1 = *(const float4*)&eo[(size_t)g1*Dc + d];
    float4 r;
    r.x = a.x + b.x + w0*c0.x + w1*c1.x;
    r.y = a.y + b.y + w0*c0.y + w1*c1.y;
    r.z = a.z + b.z + w0*c0.z + w1*c1.z;
    r.w = a.w + b.w + w0*c0.w + w1*c1.w;
    *(float4*)&out[o] = r;
}

// ---------------- launch ----------------
extern "C" void kernel_launch(void* const* d_in, const int* in_sizes, int n_in,
                              void* d_out, int out_size)
{
    const float* x   = (const float*)d_in[0];
    const float* qw  = (const float*)d_in[1];
    const float* kvw = (const float*)d_in[2];
    const float* ow  = (const float*)d_in[3];
    const float* gw  = (const float*)d_in[4];
    const float* w1  = (const float*)d_in[5];
    const float* w2  = (const float*)d_in[6];
    const float* w3  = (const float*)d_in[7];
    const float* sw1 = (const float*)d_in[8];
    const float* sw2 = (const float*)d_in[9];
    const float* sw3 = (const float*)d_in[10];
    float* out = (float*)d_out;

    float *xn,*qb,*kvb,*ao,*x2,*xn2,*hs,*sh,*hbuf,*eo,*wgt;
    __half *qwT,*kvwT,*owT,*sw1T,*sw3T,*sw2T,*w1T,*w3T,*w2T;
    int *cnt,*base,*list,*eidx,*epos;
    cudaGetSymbolAddress((void**)&xn,   g_xn);
    cudaGetSymbolAddress((void**)&qb,   g_q);
    cudaGetSymbolAddress((void**)&kvb,  g_kv);
    cudaGetSymbolAddress((void**)&ao,   g_ao);
    cudaGetSymbolAddress((void**)&x2,   g_x2);
    cudaGetSymbolAddress((void**)&xn2,  g_xn2);
    cudaGetSymbolAddress((void**)&hs,   g_hs);
    cudaGetSymbolAddress((void**)&sh,   g_sh);
    cudaGetSymbolAddress((void**)&hbuf, g_hbuf);
    cudaGetSymbolAddress((void**)&eo,   g_eo);
    cudaGetSymbolAddress((void**)&wgt,  g_wgt);
    cudaGetSymbolAddress((void**)&qwT,  g_qwT);
    cudaGetSymbolAddress((void**)&kvwT, g_kvwT);
    cudaGetSymbolAddress((void**)&owT,  g_owT);
    cudaGetSymbolAddress((void**)&sw1T, g_sw1T);
    cudaGetSymbolAddress((void**)&sw3T, g_sw3T);
    cudaGetSymbolAddress((void**)&sw2T, g_sw2T);
    cudaGetSymbolAddress((void**)&w1T,  g_w1T);
    cudaGetSymbolAddress((void**)&w3T,  g_w3T);
    cudaGetSymbolAddress((void**)&w2T,  g_w2T);
    cudaGetSymbolAddress((void**)&cnt,  g_cnt);
    cudaGetSymbolAddress((void**)&base, g_base);
    cudaGetSymbolAddress((void**)&list, g_list);
    cudaGetSymbolAddress((void**)&eidx, g_eidx);
    cudaGetSymbolAddress((void**)&epos, g_epos);

    dim3 tb(32,8);
    transp_kernel<<<dim3(Dc/32,  Dc/32, 1), tb>>>(qw,  qwT,  Dc, Dc);
    transp_kernel<<<dim3(NKVc/32,Dc/32, 1), tb>>>(kvw, kvwT, Dc, NKVc);
    transp_kernel<<<dim3(Dc/32,  Dc/32, 1), tb>>>(ow,  owT,  Dc, Dc);
    transp_kernel<<<dim3(FFc/32, Dc/32, 1), tb>>>(sw1, sw1T, Dc, FFc);
    transp_kernel<<<dim3(FFc/32, Dc/32, 1), tb>>>(sw3, sw3T, Dc, FFc);
    transp_kernel<<<dim3(Dc/32,  FFc/32,1), tb>>>(sw2, sw2T, FFc, Dc);
    transp_kernel<<<dim3(FFc/32, Dc/32, Ec), tb>>>(w1, w1T, Dc, FFc);
    transp_kernel<<<dim3(FFc/32, Dc/32, Ec), tb>>>(w3, w3T, Dc, FFc);
    transp_kernel<<<dim3(Dc/32,  FFc/32,Ec), tb>>>(w2, w2T, FFc, Dc);

    rms_kernel<<<Tc, 256>>>(x, xn);
    gemm_f16<<<dim3(Dc/64,  Tc/128, 1), 256>>>(xn, qwT,  nullptr, qb,  Dc,   Dc,
                                               nullptr, nullptr, nullptr, 0);
    gemm_f16<<<dim3(NKVc/64,Tc/128, 1), 256>>>(xn, kvwT, nullptr, kvb, NKVc, Dc,
                                               nullptr, nullptr, nullptr, 0);
    attn_kernel<<<Tc, 288>>>(qb, kvb, ao);
    gemm_f16<<<dim3(Dc/64, Tc/128, 1), 256>>>(ao, owT, x, x2, Dc, Dc,
                                              nullptr, nullptr, nullptr, 0);
    rms_kernel<<<Tc, 256>>>(x2, xn2);
    zero_cnt_kernel<<<1, 32>>>(cnt);
    gate_kernel<<<Tc/4, 128>>>(xn2, gw, cnt, list, eidx, epos, wgt);
    prefix_kernel<<<1, 32>>>(cnt, base);
    // shared expert
    gemm_dual_f16<<<dim3(FFc/64, Tc/128, 1), 256>>>(xn2, sw1T, sw3T, hs, FFc, Dc,
                                                    nullptr, nullptr, nullptr, 0);
    gemm_f16<<<dim3(Dc/64, Tc/128, 1), 256>>>(hs, sw2T, nullptr, sh, Dc, FFc,
                                              nullptr, nullptr, nullptr, 0);
    // MoE experts (sparse, gathered)
    gemm_dual_f16<<<dim3(FFc/64, Tc/128, Ec), 256>>>(xn2, w1T, w3T, hbuf, FFc, Dc,
                                                     list, cnt, base, (long)FFc*Dc);
    gemm_f16<<<dim3(Dc/64, Tc/128, Ec), 256>>>(hbuf, w2T, nullptr, eo, Dc, FFc,
                                               nullptr, cnt, base, (long)Dc*FFc);
    combine_kernel<<<Tc, 144>>>(x2, sh, eo, eidx, epos, base, wgt, out);
}